// round 15
// baseline (speedup 1.0000x reference)
#include <cuda_runtime.h>
#include <cuda_fp16.h>
#include <math.h>

#define N_NODES 50000
#define N_EDGES 1250000
#define D 64
#define L 3

#define CNT_PAD 53248       // >= 98*512, multiple of 4, zero-padded
#define SCAN_BLOCKS 98      // 98 * 512 = 50176 >= N_NODES

// Scratch (allocation-free).
__device__ float   g_agg[N_NODES * D];
__device__ __half2 g_h16[N_NODES * (D / 2)];   // fp16 hidden state (gather input)
__device__ int     g_cnt[CNT_PAD];             // zero at entry; scan3 re-zeroes
__device__ int     g_off[N_NODES + 1];
__device__ int     g_cursor[N_NODES];
__device__ int     g_part[SCAN_BLOCKS];
__device__ int     g_partscan[SCAN_BLOCKS];
__device__ int2    g_csr[N_EDGES];   // .x = src node, .y = weight bits

// ---------------------------------------------------------------------------
// Fused: copy h -> out[:,0:64], seed g_h16, and count in-degrees.
// g_cnt is zero on entry (static init on call 1; scan_part3 re-zeroes after).
__global__ void copy_count_kernel(const float* __restrict__ h,
                                  float* __restrict__ out,
                                  const int* __restrict__ dst) {
    int i = blockIdx.x * blockDim.x + threadIdx.x;

    if (i < N_EDGES / 4) {
        int4 d4 = ((const int4*)dst)[i];
        atomicAdd(&g_cnt[d4.x], 1);
        atomicAdd(&g_cnt[d4.y], 1);
        atomicAdd(&g_cnt[d4.z], 1);
        atomicAdd(&g_cnt[d4.w], 1);
    }

    if (i >= N_NODES * 16) return;
    int node = i >> 4;
    int c = i & 15;
    float4 v = ((const float4*)h)[i];
    ((float4*)(out + (size_t)node * 256))[c] = v;
    g_h16[node * 32 + c * 2 + 0] = __float22half2_rn(make_float2(v.x, v.y));
    g_h16[node * 32 + c * 2 + 1] = __float22half2_rn(make_float2(v.z, v.w));
}

// ---------------------------------------------------------------------------
// Scan phase 1: per-block (512-element) sums of g_cnt. 98 blocks x 256 thr.
__global__ void scan_part1_kernel() {
    __shared__ int sh[256];
    int t = threadIdx.x;
    int2 c = ((const int2*)g_cnt)[blockIdx.x * 256 + t];  // 512 ints/block
    sh[t] = c.x + c.y;
    __syncthreads();
    #pragma unroll
    for (int s = 128; s > 0; s >>= 1) {
        if (t < s) sh[t] += sh[t + s];
        __syncthreads();
    }
    if (t == 0) g_part[blockIdx.x] = sh[0];
}

// ---------------------------------------------------------------------------
// Scan phase 2: exclusive scan of the 98 block partials. 1 block, 128 thr.
__global__ void scan_part2_kernel() {
    __shared__ int sh[128];
    int t = threadIdx.x;
    sh[t] = (t < SCAN_BLOCKS) ? g_part[t] : 0;
    __syncthreads();
    #pragma unroll
    for (int off = 1; off < 128; off <<= 1) {
        int v = (t >= off) ? sh[t - off] : 0;
        __syncthreads();
        sh[t] += v;
        __syncthreads();
    }
    if (t < SCAN_BLOCKS) g_partscan[t] = (t == 0) ? 0 : sh[t - 1];
    if (t == 0) g_off[N_NODES] = sh[127];  // grand total (padding is zero)
}

// ---------------------------------------------------------------------------
// Scan phase 3: local exclusive scan within each 512-chunk + block offset.
// Writes g_off and g_cursor; re-zeroes g_cnt for the next graph replay.
__global__ void scan_part3_kernel() {
    __shared__ int sh[512];
    int t = threadIdx.x;
    int idx = blockIdx.x * 512 + t;
    int c = g_cnt[idx];                  // idx < 50176 <= CNT_PAD, pad reads 0
    sh[t] = c;
    __syncthreads();
    #pragma unroll
    for (int off = 1; off < 512; off <<= 1) {
        int v = (t >= off) ? sh[t - off] : 0;
        __syncthreads();
        sh[t] += v;
        __syncthreads();
    }
    int excl = ((t == 0) ? 0 : sh[t - 1]) + g_partscan[blockIdx.x];
    if (idx < N_NODES) {
        g_off[idx] = excl;
        g_cursor[idx] = excl;
    }
    g_cnt[idx] = 0;                      // self-clean for next replay
}

// ---------------------------------------------------------------------------
// CSR build: scatter edges into dst-sorted order. 4 edges/thread.
__global__ void fill_kernel(const int* __restrict__ src,
                            const int* __restrict__ dst,
                            const float* __restrict__ ew) {
    int i = blockIdx.x * blockDim.x + threadIdx.x;
    if (i >= N_EDGES / 4) return;
    int4   d4 = ((const int4*)dst)[i];
    int4   s4 = ((const int4*)src)[i];
    float4 w4 = ((const float4*)ew)[i];
    int p0 = atomicAdd(&g_cursor[d4.x], 1);
    int p1 = atomicAdd(&g_cursor[d4.y], 1);
    int p2 = atomicAdd(&g_cursor[d4.z], 1);
    int p3 = atomicAdd(&g_cursor[d4.w], 1);
    g_csr[p0] = make_int2(s4.x, __float_as_int(w4.x));
    g_csr[p1] = make_int2(s4.y, __float_as_int(w4.y));
    g_csr[p2] = make_int2(s4.z, __float_as_int(w4.z));
    g_csr[p3] = make_int2(s4.w, __float_as_int(w4.w));
}

// ---------------------------------------------------------------------------
// Pull aggregation: one warp per node, each lane owns 2 columns (half2 load
// = 4B -> 128B fully-coalesced per edge). fp32 accumulation.
// FULLY PREDICATED x8 loop: indices clamped to end-1 (always valid), OOB
// weights zeroed -> MLP=8 on every round including the tail.
__global__ void gather_kernel() {
    int gtid = blockIdx.x * blockDim.x + threadIdx.x;
    int node = gtid >> 5;
    if (node >= N_NODES) return;
    int lane = gtid & 31;

    int beg = g_off[node];
    int end = g_off[node + 1];

    float2 acc = make_float2(0.f, 0.f);

    if (beg < end) {
        int last = end - 1;
        for (int j = beg; j < end; j += 8) {
            int j0 = j;
            int j1 = min(j + 1, last);
            int j2 = min(j + 2, last);
            int j3 = min(j + 3, last);
            int j4 = min(j + 4, last);
            int j5 = min(j + 5, last);
            int j6 = min(j + 6, last);
            int j7 = min(j + 7, last);
            int2 e0 = g_csr[j0];
            int2 e1 = g_csr[j1];
            int2 e2 = g_csr[j2];
            int2 e3 = g_csr[j3];
            int2 e4 = g_csr[j4];
            int2 e5 = g_csr[j5];
            int2 e6 = g_csr[j6];
            int2 e7 = g_csr[j7];
            float2 v0 = __half22float2(g_h16[e0.x * 32 + lane]);
            float2 v1 = __half22float2(g_h16[e1.x * 32 + lane]);
            float2 v2 = __half22float2(g_h16[e2.x * 32 + lane]);
            float2 v3 = __half22float2(g_h16[e3.x * 32 + lane]);
            float2 v4 = __half22float2(g_h16[e4.x * 32 + lane]);
            float2 v5 = __half22float2(g_h16[e5.x * 32 + lane]);
            float2 v6 = __half22float2(g_h16[e6.x * 32 + lane]);
            float2 v7 = __half22float2(g_h16[e7.x * 32 + lane]);
            float w0 = __int_as_float(e0.y);
            float w1 = (j + 1 <= last) ? __int_as_float(e1.y) : 0.f;
            float w2 = (j + 2 <= last) ? __int_as_float(e2.y) : 0.f;
            float w3 = (j + 3 <= last) ? __int_as_float(e3.y) : 0.f;
            float w4 = (j + 4 <= last) ? __int_as_float(e4.y) : 0.f;
            float w5 = (j + 5 <= last) ? __int_as_float(e5.y) : 0.f;
            float w6 = (j + 6 <= last) ? __int_as_float(e6.y) : 0.f;
            float w7 = (j + 7 <= last) ? __int_as_float(e7.y) : 0.f;
            acc.x += v0.x * w0; acc.y += v0.y * w0;
            acc.x += v1.x * w1; acc.y += v1.y * w1;
            acc.x += v2.x * w2; acc.y += v2.y * w2;
            acc.x += v3.x * w3; acc.y += v3.y * w3;
            acc.x += v4.x * w4; acc.y += v4.y * w4;
            acc.x += v5.x * w5; acc.y += v5.y * w5;
            acc.x += v6.x * w6; acc.y += v6.y * w6;
            acc.x += v7.x * w7; acc.y += v7.y * w7;
        }
    }

    ((float2*)g_agg)[node * 32 + lane] = acc;
}

// ---------------------------------------------------------------------------
// Dense transform: h_next = agg @ W + b, optional tanh.
// 64-row block, 128 threads, 8x4 register tile. Writes fp32 out + fp16 g_h16.
__global__ void gemm_bias_act_kernel(const float* __restrict__ W,
                                     const float* __restrict__ b,
                                     float* __restrict__ out,
                                     int out_col_off,
                                     int do_tanh) {
    __shared__ __align__(16) float AsT[64][68];
    __shared__ __align__(16) float Wsm[64 * 64];
    __shared__ float bsh[64];

    int t = threadIdx.x;  // 128 threads
    int rowBase = blockIdx.x * 64;

    #pragma unroll
    for (int i = 0; i < 8; i++)
        ((float4*)Wsm)[t + i * 128] = ((const float4*)W)[t + i * 128];
    if (t < 64) bsh[t] = b[t];

    #pragma unroll
    for (int i = 0; i < 8; i++) {
        int idx = t + i * 128;
        int row = idx >> 4;
        int c4  = idx & 15;
        int grow = rowBase + row;
        float4 v = (grow < N_NODES) ? ((const float4*)g_agg)[grow * 16 + c4]
                                    : make_float4(0.f, 0.f, 0.f, 0.f);
        AsT[c4 * 4 + 0][row] = v.x;
        AsT[c4 * 4 + 1][row] = v.y;
        AsT[c4 * 4 + 2][row] = v.z;
        AsT[c4 * 4 + 3][row] = v.w;
    }
    __syncthreads();

    int tx = t & 15;
    int ty = t >> 4;

    float acc[8][4];
    #pragma unroll
    for (int i = 0; i < 8; i++)
        #pragma unroll
        for (int j = 0; j < 4; j++)
            acc[i][j] = bsh[tx * 4 + j];

    #pragma unroll 8
    for (int k = 0; k < 64; k++) {
        float4 alo = *(const float4*)&AsT[k][ty * 8];
        float4 ahi = *(const float4*)&AsT[k][ty * 8 + 4];
        float4 w   = *(const float4*)&Wsm[k * 64 + tx * 4];
        acc[0][0] += alo.x * w.x; acc[0][1] += alo.x * w.y; acc[0][2] += alo.x * w.z; acc[0][3] += alo.x * w.w;
        acc[1][0] += alo.y * w.x; acc[1][1] += alo.y * w.y; acc[1][2] += alo.y * w.z; acc[1][3] += alo.y * w.w;
        acc[2][0] += alo.z * w.x; acc[2][1] += alo.z * w.y; acc[2][2] += alo.z * w.z; acc[2][3] += alo.z * w.w;
        acc[3][0] += alo.w * w.x; acc[3][1] += alo.w * w.y; acc[3][2] += alo.w * w.z; acc[3][3] += alo.w * w.w;
        acc[4][0] += ahi.x * w.x; acc[4][1] += ahi.x * w.y; acc[4][2] += ahi.x * w.z; acc[4][3] += ahi.x * w.w;
        acc[5][0] += ahi.y * w.x; acc[5][1] += ahi.y * w.y; acc[5][2] += ahi.y * w.z; acc[5][3] += ahi.y * w.w;
        acc[6][0] += ahi.z * w.x; acc[6][1] += ahi.z * w.y; acc[6][2] += ahi.z * w.z; acc[6][3] += ahi.z * w.w;
        acc[7][0] += ahi.w * w.x; acc[7][1] += ahi.w * w.y; acc[7][2] += ahi.w * w.z; acc[7][3] += ahi.w * w.w;
    }

    #pragma unroll
    for (int i = 0; i < 8; i++) {
        int grow = rowBase + ty * 8 + i;
        if (grow >= N_NODES) continue;
        float4 r = make_float4(acc[i][0], acc[i][1], acc[i][2], acc[i][3]);
        if (do_tanh) {
            r.x = tanhf(r.x); r.y = tanhf(r.y); r.z = tanhf(r.z); r.w = tanhf(r.w);
        }
        g_h16[grow * 32 + tx * 2 + 0] = __float22half2_rn(make_float2(r.x, r.y));
        g_h16[grow * 32 + tx * 2 + 1] = __float22half2_rn(make_float2(r.z, r.w));
        *(float4*)(out + (size_t)grow * 256 + out_col_off + tx * 4) = r;
    }
}

// ---------------------------------------------------------------------------
extern "C" void kernel_launch(void* const* d_in, const int* in_sizes, int n_in,
                              void* d_out, int out_size) {
    const float* h   = (const float*)d_in[0];  // [N, 64]
    const float* ew  = (const float*)d_in[1];  // [E]
    const float* Ws  = (const float*)d_in[2];  // [3, 64, 64]
    const float* bs  = (const float*)d_in[3];  // [3, 64]
    const int*   src = (const int*)d_in[4];    // [E]
    const int*   dst = (const int*)d_in[5];    // [E]
    float*       out = (float*)d_out;          // [N, 256]

    // Fused copy + degree count (g_cnt zero on entry; scan3 re-zeroes).
    copy_count_kernel<<<(N_NODES * 16 + 255) / 256, 256>>>(h, out, dst);

    // Parallel 3-phase exclusive scan -> g_off / g_cursor.
    scan_part1_kernel<<<SCAN_BLOCKS, 256>>>();
    scan_part2_kernel<<<1, 128>>>();
    scan_part3_kernel<<<SCAN_BLOCKS, 512>>>();

    // CSR fill (by dst).
    fill_kernel<<<(N_EDGES / 4 + 255) / 256, 256>>>(src, dst, ew);

    for (int l = 0; l < L; l++) {
        gather_kernel<<<(N_NODES * 32 + 255) / 256, 256>>>();
        gemm_bias_act_kernel<<<(N_NODES + 63) / 64, 128>>>(
            Ws + l * 64 * 64, bs + l * 64, out, (l + 1) * 64, (l < L - 1) ? 1 : 0);
    }
}